// round 10
// baseline (speedup 1.0000x reference)
#include <cuda_runtime.h>
#include <cuda_fp16.h>
#include <cstdint>
#include <math.h>

// Problem constants
#define BATCH 2
#define SEQ   1024
#define TOK   (BATCH*SEQ)      // 2048
#define DMODEL 1024
#define NHEAD 16
#define DK    64
#define FF    4096
#define NLAYER 4
#define LNEPS 1e-5f

#define H_ELEMS ((size_t)TOK * DMODEL)
#define AW_PER_LAYER ((size_t)BATCH * NHEAD * SEQ * SEQ)

// ------------------------- scratch (static device globals) -------------------------
__device__ float g_h  [TOK * DMODEL];
__device__ float g_q  [TOK * DMODEL];
__device__ float g_k  [TOK * DMODEL];
__device__ float g_v  [TOK * DMODEL];
__device__ float g_ctx[TOK * DMODEL];
__device__ float g_res[TOK * DMODEL];
__device__ float g_ff [TOK * FF];

// ------------------------------ fp16 / mma helpers ----------------------------------
__device__ __forceinline__ uint32_t pack_half2(float x, float y) {
    __half2 h = __floats2half2_rn(x, y);
    return *(uint32_t*)&h;
}
__device__ __forceinline__ uint32_t cvta_smem(const void* p) {
    return (uint32_t)__cvta_generic_to_shared(p);
}
__device__ __forceinline__ void mma16816(float c[4], const uint32_t a[4], const uint32_t b[2]) {
    asm volatile(
        "mma.sync.aligned.m16n8k16.row.col.f32.f16.f16.f32 "
        "{%0,%1,%2,%3}, {%4,%5,%6,%7}, {%8,%9}, {%0,%1,%2,%3};"
        : "+f"(c[0]), "+f"(c[1]), "+f"(c[2]), "+f"(c[3])
        : "r"(a[0]), "r"(a[1]), "r"(a[2]), "r"(a[3]), "r"(b[0]), "r"(b[1]));
}
__device__ __forceinline__ void ldsm_x4(uint32_t& r0, uint32_t& r1, uint32_t& r2, uint32_t& r3,
                                        uint32_t addr) {
    asm volatile("ldmatrix.sync.aligned.m8n8.x4.shared.b16 {%0,%1,%2,%3}, [%4];"
                 : "=r"(r0), "=r"(r1), "=r"(r2), "=r"(r3) : "r"(addr));
}
__device__ __forceinline__ void ldsm_x4_t(uint32_t& r0, uint32_t& r1, uint32_t& r2, uint32_t& r3,
                                          uint32_t addr) {
    asm volatile("ldmatrix.sync.aligned.m8n8.x4.trans.shared.b16 {%0,%1,%2,%3}, [%4];"
                 : "=r"(r0), "=r"(r1), "=r"(r2), "=r"(r3) : "r"(addr));
}

// ===================== fp16 ldmatrix GEMM core (64x128 tile, 2 CTAs/SM) ==============
// C[M,N] = A[M,K] @ B[K,N] + bias (ReLU optional). 256 thr, BM=64, BN=128, BK=32.
// 8 warps as 2(M) x 4(N), warp tile 32x32. A smem [m][k] pad 40, B smem [k][n] pad 136.
// Loop order: storeS(next) -> loadG(next+1) -> mma(cur) -> sync.
#define GBM  64
#define GBK  32
#define GBKP 40
#define GBNP 136

template <int RELU>
__device__ __forceinline__ void gemm_core_f16(
    const float* __restrict__ A,
    const float* __restrict__ B,
    const float* __restrict__ bias,
    float* __restrict__ C,
    int N, int K)
{
    __shared__ __half As[2][GBM * GBKP];
    __shared__ __half Bs[2][GBK * GBNP];

    const int tid = threadIdx.x;
    const int m0 = blockIdx.y * GBM;
    const int n0 = blockIdx.x * 128;
    A += (size_t)m0 * K;
    B += n0;
    C += (size_t)m0 * N + n0;
    bias += n0;

    float4 pa[2], pb[4];
    const int NC = K / GBK;

    auto loadG = [&](int c) {
        #pragma unroll
        for (int t = 0; t < 2; t++) {
            int i = tid + t * 256;
            int r = i >> 3, kg = (i & 7) * 4;
            pa[t] = *(const float4*)(A + (size_t)r * K + c * GBK + kg);
        }
        #pragma unroll
        for (int t = 0; t < 4; t++) {
            int i = tid + t * 256;
            int r = i >> 5, cc = (i & 31) * 4;
            pb[t] = *(const float4*)(B + (size_t)(c * GBK + r) * N + cc);
        }
    };
    auto storeS = [&](int buf) {
        #pragma unroll
        for (int t = 0; t < 2; t++) {
            int i = tid + t * 256;
            int r = i >> 3, kg = (i & 7) * 4;
            *(uint2*)&As[buf][r * GBKP + kg] =
                make_uint2(pack_half2(pa[t].x, pa[t].y), pack_half2(pa[t].z, pa[t].w));
        }
        #pragma unroll
        for (int t = 0; t < 4; t++) {
            int i = tid + t * 256;
            int r = i >> 5, cc = (i & 31) * 4;
            *(uint2*)&Bs[buf][r * GBNP + cc] =
                make_uint2(pack_half2(pb[t].x, pb[t].y), pack_half2(pb[t].z, pb[t].w));
        }
    };

    const int w = tid >> 5, lane = tid & 31;
    const int wm = (w & 1) * 32, wn = (w >> 1) * 32;
    const int g = lane >> 2, tg = lane & 3;
    const int lr = lane & 15;                 // ldmatrix row-within-16
    const int lc = (lane >> 4) * 8;           // ldmatrix col-group

    float acc[2][4][4];
    #pragma unroll
    for (int ms = 0; ms < 2; ms++)
        #pragma unroll
        for (int ns = 0; ns < 4; ns++)
            #pragma unroll
            for (int r = 0; r < 4; r++) acc[ms][ns][r] = 0.0f;

    loadG(0);
    storeS(0);
    if (NC > 1) loadG(1);
    __syncthreads();

    for (int c = 0; c < NC; c++) {
        int buf = c & 1;
        if (c + 1 < NC) storeS(buf ^ 1);   // registers hold chunk c+1
        if (c + 2 < NC) loadG(c + 2);      // refill registers AFTER storing

        const uint32_t baseA = cvta_smem(&As[buf][0]);
        const uint32_t baseB = cvta_smem(&Bs[buf][0]);
        #pragma unroll
        for (int ks = 0; ks < 2; ks++) {
            uint32_t af[2][4], bf[4][2];
            #pragma unroll
            for (int ms = 0; ms < 2; ms++) {
                uint32_t ad = baseA + 2u * ((wm + ms * 16 + lr) * GBKP + ks * 16 + lc);
                ldsm_x4(af[ms][0], af[ms][1], af[ms][2], af[ms][3], ad);
            }
            #pragma unroll
            for (int p = 0; p < 2; p++) {
                int row = ks * 16 + lr;
                int col = wn + p * 16 + lc;
                uint32_t ad = baseB + 2u * (row * GBNP + col);
                ldsm_x4_t(bf[2 * p][0], bf[2 * p][1], bf[2 * p + 1][0], bf[2 * p + 1][1], ad);
            }
            #pragma unroll
            for (int ms = 0; ms < 2; ms++)
                #pragma unroll
                for (int ns = 0; ns < 4; ns++)
                    mma16816(acc[ms][ns], af[ms], bf[ns]);
        }
        __syncthreads();
    }

    #pragma unroll
    for (int ms = 0; ms < 2; ms++) {
        #pragma unroll
        for (int ns = 0; ns < 4; ns++) {
            int row = wm + ms * 16 + g;
            int col = wn + ns * 8 + tg * 2;
            float b0 = bias[col], b1 = bias[col + 1];
            float v0 = acc[ms][ns][0] + b0;
            float v1 = acc[ms][ns][1] + b1;
            float v2 = acc[ms][ns][2] + b0;
            float v3 = acc[ms][ns][3] + b1;
            if (RELU) {
                v0 = fmaxf(v0, 0.0f); v1 = fmaxf(v1, 0.0f);
                v2 = fmaxf(v2, 0.0f); v3 = fmaxf(v3, 0.0f);
            }
            *(float2*)&C[(size_t)row * N + col] = make_float2(v0, v1);
            *(float2*)&C[(size_t)(row + 8) * N + col] = make_float2(v2, v3);
        }
    }
}

struct QKV3 {
    const float* W[3];
    const float* b[3];
    float* o[3];
};

template <int RELU>
__global__ __launch_bounds__(256, 2) void gemm_f16(const float* __restrict__ A,
                                                   const float* __restrict__ B,
                                                   const float* __restrict__ bias,
                                                   float* __restrict__ C, int N, int K) {
    gemm_core_f16<RELU>(A, B, bias, C, N, K);
}

__global__ __launch_bounds__(256, 2) void gemm_qkv_f16(const float* __restrict__ A, QKV3 p) {
    int z = blockIdx.z;
    gemm_core_f16<0>(A, p.W[z], p.b[z], p.o[z], DMODEL, DMODEL);
}

// ================= fused attention (fp16 + ldmatrix, fp32 softmax/output) ============
// grid (SEQ/128, BATCH*NHEAD), 256 threads. Two-pass softmax; P written once (fp32)
// to d_out and consumed from smem (fp16) for P@V.
#define ATT_HALVES (128*72 + 128*72 + 128*72 + 128*136)
#define ATT_SMEM   (ATT_HALVES*2 + (4*128 + 128 + 128)*4)

__global__ __launch_bounds__(256) void attn_fused(const float* __restrict__ q,
                                                  const float* __restrict__ k,
                                                  const float* __restrict__ v,
                                                  float* __restrict__ aw,
                                                  float* __restrict__ ctx) {
    extern __shared__ char smc[];
    __half* Qs = (__half*)smc;              // [128][72]
    __half* Ks = Qs + 128 * 72;             // [128][72]
    __half* Vs = Ks + 128 * 72;             // [128][72]
    __half* Ps = Vs + 128 * 72;             // [128][136]
    float* red  = (float*)(Ps + 128 * 136); // [4][128]
    float* mrow = red + 4 * 128;
    float* srow = mrow + 128;

    const int tid = threadIdx.x;
    const int mt = blockIdx.x, bh = blockIdx.y;
    const int b = bh >> 4, hh = bh & 15;
    const float* qb = q + (size_t)(b * SEQ + mt * 128) * DMODEL + hh * DK;
    const float* kb = k + (size_t)b * SEQ * DMODEL + hh * DK;
    const float* vb = v + (size_t)b * SEQ * DMODEL + hh * DK;
    float* awb = aw + (size_t)bh * SEQ * SEQ + (size_t)(mt * 128) * SEQ;

    const int w = tid >> 5, lane = tid & 31, g = lane >> 2, tg = lane & 3;
    const int wm = (w & 1) * 64, wn = (w >> 1) * 32, wni = w >> 1;   // S tile 2x4 warps
    const int wm2 = (w & 3) * 32, wn2 = (w >> 2) * 32;               // PV tile 4x2 warps
    const int lr = lane & 15;
    const int lc = (lane >> 4) * 8;
    const int nB = (lane & 7) + ((lane >> 4) << 3);   // non-trans B: n row
    const int kB = ((lane >> 3) & 1) * 8;             // non-trans B: k col group

    const uint32_t uQs = cvta_smem(Qs);
    const uint32_t uKs = cvta_smem(Ks);
    const uint32_t uVs = cvta_smem(Vs);
    const uint32_t uPs = cvta_smem(Ps);

    // ---- load Q tile once ----
    #pragma unroll
    for (int t = 0; t < 8; t++) {
        int i = tid + t * 256;
        int r = i >> 4, c = (i & 15) * 4;
        float4 x = *(const float4*)(qb + (size_t)r * DMODEL + c);
        *(uint2*)&Qs[r * 72 + c] = make_uint2(pack_half2(x.x, x.y), pack_half2(x.z, x.w));
    }
    if (tid < 128) { mrow[tid] = -INFINITY; srow[tid] = 0.0f; }
    __syncthreads();

    // =========================== PASS 1: row max & sum ==============================
    for (int kt = 0; kt < 8; kt++) {
        #pragma unroll
        for (int t = 0; t < 8; t++) {
            int i = tid + t * 256;
            int r = i >> 4, c = (i & 15) * 4;
            float4 x = *(const float4*)(kb + (size_t)(kt * 128 + r) * DMODEL + c);
            *(uint2*)&Ks[r * 72 + c] = make_uint2(pack_half2(x.x, x.y), pack_half2(x.z, x.w));
        }
        __syncthreads();

        float acc[4][4][4];
        #pragma unroll
        for (int ms = 0; ms < 4; ms++)
            #pragma unroll
            for (int ns = 0; ns < 4; ns++)
                #pragma unroll
                for (int r = 0; r < 4; r++) acc[ms][ns][r] = 0.0f;

        #pragma unroll
        for (int ks = 0; ks < 4; ks++) {
            uint32_t af[4][4], bf[4][2];
            #pragma unroll
            for (int ms = 0; ms < 4; ms++) {
                uint32_t ad = uQs + 2u * ((wm + ms * 16 + lr) * 72 + ks * 16 + lc);
                ldsm_x4(af[ms][0], af[ms][1], af[ms][2], af[ms][3], ad);
            }
            #pragma unroll
            for (int p = 0; p < 2; p++) {
                int n = wn + p * 16 + nB;
                uint32_t ad = uKs + 2u * (n * 72 + ks * 16 + kB);
                ldsm_x4(bf[2 * p][0], bf[2 * p][1], bf[2 * p + 1][0], bf[2 * p + 1][1], ad);
            }
            #pragma unroll
            for (int ms = 0; ms < 4; ms++)
                #pragma unroll
                for (int ns = 0; ns < 4; ns++)
                    mma16816(acc[ms][ns], af[ms], bf[ns]);
        }
        #pragma unroll
        for (int ms = 0; ms < 4; ms++)
            #pragma unroll
            for (int ns = 0; ns < 4; ns++)
                #pragma unroll
                for (int r = 0; r < 4; r++) acc[ms][ns][r] *= 0.125f;

        // row max of this tile
        #pragma unroll
        for (int ms = 0; ms < 4; ms++) {
            #pragma unroll
            for (int half = 0; half < 2; half++) {
                float rm = -INFINITY;
                #pragma unroll
                for (int ns = 0; ns < 4; ns++)
                    rm = fmaxf(rm, fmaxf(acc[ms][ns][half * 2], acc[ms][ns][half * 2 + 1]));
                rm = fmaxf(rm, __shfl_xor_sync(0xffffffffu, rm, 1));
                rm = fmaxf(rm, __shfl_xor_sync(0xffffffffu, rm, 2));
                if (tg == 0) red[wni * 128 + wm + ms * 16 + half * 8 + g] = rm;
            }
        }
        __syncthreads();
        if (tid < 128) {
            float tm = fmaxf(fmaxf(red[tid], red[128 + tid]),
                             fmaxf(red[256 + tid], red[384 + tid]));
            float mo = mrow[tid];
            float mn = fmaxf(mo, tm);
            srow[tid] *= expf(mo - mn);
            mrow[tid] = mn;
        }
        __syncthreads();
        // row sum of exp
        #pragma unroll
        for (int ms = 0; ms < 4; ms++) {
            #pragma unroll
            for (int half = 0; half < 2; half++) {
                int row = wm + ms * 16 + half * 8 + g;
                float mr = mrow[row];
                float rs = 0.0f;
                #pragma unroll
                for (int ns = 0; ns < 4; ns++)
                    rs += expf(acc[ms][ns][half * 2] - mr) + expf(acc[ms][ns][half * 2 + 1] - mr);
                rs += __shfl_xor_sync(0xffffffffu, rs, 1);
                rs += __shfl_xor_sync(0xffffffffu, rs, 2);
                if (tg == 0) red[wni * 128 + row] = rs;
            }
        }
        __syncthreads();
        if (tid < 128)
            srow[tid] += red[tid] + red[128 + tid] + red[256 + tid] + red[384 + tid];
        __syncthreads();
    }

    if (tid < 128) srow[tid] = 1.0f / srow[tid];
    __syncthreads();

    // ================== PASS 2: recompute S, write P, accumulate P@V ================
    float acc2[2][4][4];
    #pragma unroll
    for (int ms = 0; ms < 2; ms++)
        #pragma unroll
        for (int ns = 0; ns < 4; ns++)
            #pragma unroll
            for (int r = 0; r < 4; r++) acc2[ms][ns][r] = 0.0f;

    for (int kt = 0; kt < 8; kt++) {
        #pragma unroll
        for (int t = 0; t < 8; t++) {
            int i = tid + t * 256;
            int r = i >> 4, c = (i & 15) * 4;
            float4 x = *(const float4*)(kb + (size_t)(kt * 128 + r) * DMODEL + c);
            *(uint2*)&Ks[r * 72 + c] = make_uint2(pack_half2(x.x, x.y), pack_half2(x.z, x.w));
            float4 y = *(const float4*)(vb + (size_t)(kt * 128 + r) * DMODEL + c);
            *(uint2*)&Vs[r * 72 + c] = make_uint2(pack_half2(y.x, y.y), pack_half2(y.z, y.w));
        }
        __syncthreads();

        float acc[4][4][4];
        #pragma unroll
        for (int ms = 0; ms < 4; ms++)
            #pragma unroll
            for (int ns = 0; ns < 4; ns++)
                #pragma unroll
                for (int r = 0; r < 4; r++) acc[ms][ns][r] = 0.0f;

        #pragma unroll
        for (int ks = 0; ks < 4; ks++) {
            uint32_t af[4][4], bf[4][2];
            #pragma unroll
            for (int ms = 0; ms < 4; ms++) {
                uint32_t ad = uQs + 2u * ((wm + ms * 16 + lr) * 72 + ks * 16 + lc);
                ldsm_x4(af[ms][0], af[ms][1], af[ms][2], af[ms][3], ad);
            }
            #pragma unroll
            for (int p = 0; p < 2; p++) {
                int n = wn + p * 16 + nB;
                uint32_t ad = uKs + 2u * (n * 72 + ks * 16 + kB);
                ldsm_x4(bf[2 * p][0], bf[2 * p][1], bf[2 * p + 1][0], bf[2 * p + 1][1], ad);
            }
            #pragma unroll
            for (int ms = 0; ms < 4; ms++)
                #pragma unroll
                for (int ns = 0; ns < 4; ns++)
                    mma16816(acc[ms][ns], af[ms], bf[ns]);
        }

        // P = exp(S*scale - m) * (1/sum) -> smem fp16 + gmem fp32
        #pragma unroll
        for (int ms = 0; ms < 4; ms++) {
            int row0 = wm + ms * 16 + g;
            int row1 = row0 + 8;
            float m0 = mrow[row0], s0 = srow[row0];
            float m1 = mrow[row1], s1 = srow[row1];
            #pragma unroll
            for (int ns = 0; ns < 4; ns++) {
                int col = wn + ns * 8 + tg * 2;
                float p0 = expf(acc[ms][ns][0] * 0.125f - m0) * s0;
                float p1 = expf(acc[ms][ns][1] * 0.125f - m0) * s0;
                float p2 = expf(acc[ms][ns][2] * 0.125f - m1) * s1;
                float p3 = expf(acc[ms][ns][3] * 0.125f - m1) * s1;
                *(uint32_t*)&Ps[row0 * 136 + col] = pack_half2(p0, p1);
                *(uint32_t*)&Ps[row1 * 136 + col] = pack_half2(p2, p3);
                *(float2*)&awb[(size_t)row0 * SEQ + kt * 128 + col] = make_float2(p0, p1);
                *(float2*)&awb[(size_t)row1 * SEQ + kt * 128 + col] = make_float2(p2, p3);
            }
        }
        __syncthreads();

        // ctx += P @ V   (A = Ps [q][tok], B = Vs [tok][dim] via trans ldmatrix)
        #pragma unroll
        for (int ks = 0; ks < 8; ks++) {
            uint32_t af[2][4], bf[4][2];
            #pragma unroll
            for (int ms = 0; ms < 2; ms++) {
                uint32_t ad = uPs + 2u * ((wm2 + ms * 16 + lr) * 136 + ks * 16 + lc);
                ldsm_x4(af[ms][0], af[ms][1], af[ms][2], af[ms][3], ad);
            }
            #pragma unroll
            for (int p = 0; p < 2; p++) {
                int row = ks * 16 + lr;
                int col = wn2 + p * 16 + lc;
                uint32_t ad = uVs + 2u * (row * 72 + col);
                ldsm_x4_t(bf[2 * p][0], bf[2 * p][1], bf[2 * p + 1][0], bf[2 * p + 1][1], ad);
            }
            #pragma unroll
            for (int ms = 0; ms < 2; ms++)
                #pragma unroll
                for (int ns = 0; ns < 4; ns++)
                    mma16816(acc2[ms][ns], af[ms], bf[ns]);
        }
        __syncthreads();
    }

    // ---- write ctx tile ----
    float* cb = ctx + (size_t)(b * SEQ + mt * 128) * DMODEL + hh * DK;
    #pragma unroll
    for (int ms = 0; ms < 2; ms++) {
        #pragma unroll
        for (int ns = 0; ns < 4; ns++) {
            int row = wm2 + ms * 16 + g;
            int col = wn2 + ns * 8 + tg * 2;
            *(float2*)&cb[(size_t)row * DMODEL + col] =
                make_float2(acc2[ms][ns][0], acc2[ms][ns][1]);
            *(float2*)&cb[(size_t)(row + 8) * DMODEL + col] =
                make_float2(acc2[ms][ns][2], acc2[ms][ns][3]);
        }
    }
}

// ------------------------- embedding + positional encoding -------------------------
__global__ void embed_kernel(const int* __restrict__ ids, const float* __restrict__ emb,
                             float* __restrict__ h) {
    int token = blockIdx.x;
    int d = blockIdx.y * 256 + threadIdx.x;
    int s = token & (SEQ - 1);
    int id = ids[token];
    float c_even = (float)((d >> 1) << 1);
    float div = __expf(c_even * (-logf(10000.0f) / (float)DMODEL));
    float ang = (float)s * div;
    float pe = (d & 1) ? cosf(ang) : sinf(ang);
    h[(size_t)token * DMODEL + d] = emb[(size_t)id * DMODEL + d] * 32.0f + pe;
}

// ------------------------- fused residual-add + LayerNorm ---------------------------
__global__ void add_ln_kernel(const float* __restrict__ x, const float* __restrict__ r,
                              const float* __restrict__ g, const float* __restrict__ b,
                              float* __restrict__ out) {
    const size_t row = blockIdx.x;
    const int tid = threadIdx.x;
    __shared__ float red[256];
    __shared__ float s_mu, s_rinv;
    float v[4];
    float s = 0.0f;
    #pragma unroll
    for (int i = 0; i < 4; i++) {
        int c = tid + i * 256;
        v[i] = x[row * DMODEL + c] + r[row * DMODEL + c];
        s += v[i];
    }
    red[tid] = s; __syncthreads();
    for (int t = 128; t > 0; t >>= 1) { if (tid < t) red[tid] += red[tid + t]; __syncthreads(); }
    if (tid == 0) s_mu = red[0] * (1.0f / DMODEL);
    __syncthreads();
    float mu = s_mu;
    float sq = 0.0f;
    #pragma unroll
    for (int i = 0; i < 4; i++) { float d = v[i] - mu; sq += d * d; }
    red[tid] = sq; __syncthreads();
    for (int t = 128; t > 0; t >>= 1) { if (tid < t) red[tid] += red[tid + t]; __syncthreads(); }
    if (tid == 0) s_rinv = rsqrtf(red[0] * (1.0f / DMODEL) + LNEPS);
    __syncthreads();
    float rinv = s_rinv;
    #pragma unroll
    for (int i = 0; i < 4; i++) {
        int c = tid + i * 256;
        out[row * DMODEL + c] = (v[i] - mu) * rinv * g[c] + b[c];
    }
}

// ====================================================================================
extern "C" void kernel_launch(void* const* d_in, const int* in_sizes, int n_in,
                              void* d_out, int out_size) {
    const int*   ids  = (const int*)  d_in[0];
    const float* emb  = (const float*)d_in[1];
    const float* Wq   = (const float*)d_in[2];
    const float* bq   = (const float*)d_in[3];
    const float* Wk   = (const float*)d_in[4];
    const float* bk   = (const float*)d_in[5];
    const float* Wv   = (const float*)d_in[6];
    const float* bv   = (const float*)d_in[7];
    const float* Wo   = (const float*)d_in[8];
    const float* bo   = (const float*)d_in[9];
    const float* W1   = (const float*)d_in[10];
    const float* b1   = (const float*)d_in[11];
    const float* W2   = (const float*)d_in[12];
    const float* b2   = (const float*)d_in[13];
    const float* ln1g = (const float*)d_in[14];
    const float* ln1b = (const float*)d_in[15];
    const float* ln2g = (const float*)d_in[16];
    const float* ln2b = (const float*)d_in[17];

    float* out = (float*)d_out;

    float *h, *q, *k, *v, *ctx, *res, *ff;
    cudaGetSymbolAddress((void**)&h,   g_h);
    cudaGetSymbolAddress((void**)&q,   g_q);
    cudaGetSymbolAddress((void**)&k,   g_k);
    cudaGetSymbolAddress((void**)&v,   g_v);
    cudaGetSymbolAddress((void**)&ctx, g_ctx);
    cudaGetSymbolAddress((void**)&res, g_res);
    cudaGetSymbolAddress((void**)&ff,  g_ff);

    cudaFuncSetAttribute(attn_fused, cudaFuncAttributeMaxDynamicSharedMemorySize, ATT_SMEM);

    embed_kernel<<<dim3(TOK, DMODEL / 256), 256>>>(ids, emb, h);

    dim3 gDD(DMODEL / 128, TOK / GBM);       // (8, 32)
    dim3 gDF(FF / 128, TOK / GBM);           // (32, 32)
    dim3 gQKV(DMODEL / 128, TOK / GBM, 3);   // (8, 32, 3)
    dim3 gFA(SEQ / 128, BATCH * NHEAD);      // (8, 32)

    for (int l = 0; l < NLAYER; l++) {
        const float* Wo_l = Wo + (size_t)l * DMODEL * DMODEL;
        const float* W1_l = W1 + (size_t)l * DMODEL * FF;
        const float* W2_l = W2 + (size_t)l * FF * DMODEL;

        float* aw = out + H_ELEMS + (size_t)l * AW_PER_LAYER;

        QKV3 p;
        p.W[0] = Wq + (size_t)l * DMODEL * DMODEL;
        p.W[1] = Wk + (size_t)l * DMODEL * DMODEL;
        p.W[2] = Wv + (size_t)l * DMODEL * DMODEL;
        p.b[0] = bq + (size_t)l * DMODEL;
        p.b[1] = bk + (size_t)l * DMODEL;
        p.b[2] = bv + (size_t)l * DMODEL;
        p.o[0] = q; p.o[1] = k; p.o[2] = v;

        gemm_qkv_f16<<<gQKV, 256>>>(h, p);

        attn_fused<<<gFA, 256, ATT_SMEM>>>(q, k, v, aw, ctx);

        gemm_f16<0><<<gDD, 256>>>(ctx, Wo_l, bo + (size_t)l * DMODEL, res, DMODEL, DMODEL);
        add_ln_kernel<<<TOK, 256>>>(h, res, ln1g + (size_t)l * DMODEL, ln1b + (size_t)l * DMODEL, h);

        gemm_f16<1><<<gDF, 256>>>(h, W1_l, b1 + (size_t)l * FF, ff, FF, DMODEL);
        gemm_f16<0><<<gDD, 256>>>(ff, W2_l, b2 + (size_t)l * DMODEL, res, DMODEL, FF);

        float* dst = (l == NLAYER - 1) ? out : h;
        add_ln_kernel<<<TOK, 256>>>(h, res, ln2g + (size_t)l * DMODEL, ln2b + (size_t)l * DMODEL, dst);
    }
}

// round 11
// speedup vs baseline: 1.1998x; 1.1998x over previous
#include <cuda_runtime.h>
#include <cuda_fp16.h>
#include <cstdint>
#include <math.h>

// Problem constants
#define BATCH 2
#define SEQ   1024
#define TOK   (BATCH*SEQ)      // 2048
#define DMODEL 1024
#define NHEAD 16
#define DK    64
#define FF    4096
#define NLAYER 4
#define LNEPS 1e-5f

#define H_ELEMS ((size_t)TOK * DMODEL)
#define AW_PER_LAYER ((size_t)BATCH * NHEAD * SEQ * SEQ)

// ------------------------- scratch (static device globals) -------------------------
__device__ float g_h  [TOK * DMODEL];
__device__ float g_res[TOK * DMODEL];

__device__ __half g_h16  [TOK * DMODEL];
__device__ __half g_q16  [TOK * DMODEL];
__device__ __half g_k16  [TOK * DMODEL];
__device__ __half g_v16  [TOK * DMODEL];
__device__ __half g_ctx16[TOK * DMODEL];
__device__ __half g_ff16 [TOK * FF];

// fp16 weight copies (converted once per launch)
__device__ __half g_wq16[NLAYER * DMODEL * DMODEL];
__device__ __half g_wk16[NLAYER * DMODEL * DMODEL];
__device__ __half g_wv16[NLAYER * DMODEL * DMODEL];
__device__ __half g_wo16[NLAYER * DMODEL * DMODEL];
__device__ __half g_w116[NLAYER * DMODEL * FF];
__device__ __half g_w216[NLAYER * FF * DMODEL];

// ------------------------------ helpers --------------------------------------------
__device__ __forceinline__ uint32_t pack_half2(float x, float y) {
    __half2 h = __floats2half2_rn(x, y);
    return *(uint32_t*)&h;
}
__device__ __forceinline__ uint32_t cvta_smem(const void* p) {
    return (uint32_t)__cvta_generic_to_shared(p);
}
__device__ __forceinline__ void mma16816(float c[4], const uint32_t a[4], const uint32_t b[2]) {
    asm volatile(
        "mma.sync.aligned.m16n8k16.row.col.f32.f16.f16.f32 "
        "{%0,%1,%2,%3}, {%4,%5,%6,%7}, {%8,%9}, {%0,%1,%2,%3};"
        : "+f"(c[0]), "+f"(c[1]), "+f"(c[2]), "+f"(c[3])
        : "r"(a[0]), "r"(a[1]), "r"(a[2]), "r"(a[3]), "r"(b[0]), "r"(b[1]));
}
__device__ __forceinline__ void ldsm_x4(uint32_t& r0, uint32_t& r1, uint32_t& r2, uint32_t& r3,
                                        uint32_t addr) {
    asm volatile("ldmatrix.sync.aligned.m8n8.x4.shared.b16 {%0,%1,%2,%3}, [%4];"
                 : "=r"(r0), "=r"(r1), "=r"(r2), "=r"(r3) : "r"(addr));
}
__device__ __forceinline__ void ldsm_x4_t(uint32_t& r0, uint32_t& r1, uint32_t& r2, uint32_t& r3,
                                          uint32_t addr) {
    asm volatile("ldmatrix.sync.aligned.m8n8.x4.trans.shared.b16 {%0,%1,%2,%3}, [%4];"
                 : "=r"(r0), "=r"(r1), "=r"(r2), "=r"(r3) : "r"(addr));
}
__device__ __forceinline__ void cp_async16(uint32_t dst, const void* src) {
    asm volatile("cp.async.cg.shared.global [%0], [%1], 16;" :: "r"(dst), "l"(src));
}
#define CP_COMMIT() asm volatile("cp.async.commit_group;" ::: "memory")
#define CP_WAIT(n)  asm volatile("cp.async.wait_group %0;" :: "n"(n) : "memory")

// ------------------------- bulk fp32 -> fp16 conversion ----------------------------
__global__ void f32to16(const float* __restrict__ s, __half* __restrict__ d, int n4) {
    int i = blockIdx.x * 256 + threadIdx.x;
    if (i < n4) {
        float4 v = *(const float4*)(s + (size_t)i * 4);
        *(uint2*)(d + (size_t)i * 4) =
            make_uint2(pack_half2(v.x, v.y), pack_half2(v.z, v.w));
    }
}

// ===================== fp16 cp.async GEMM (64x128x64, 3 stages, 2 CTAs/SM) ==========
// C = A[M,K] @ B[K,N] + bias. A,B fp16 gmem. 256 thr, 8 warps 2(M)x4(N), warp 32x32.
#define GBM   64
#define GBK   64
#define GAP   72     // A row pitch (halves): 144B, 9x16B, conflict-free
#define GBP   136    // B row pitch (halves): 272B, 17x16B
#define NSTG  3
#define A_STG (GBM*GAP)
#define B_STG (GBK*GBP)
#define GSMEM ((NSTG*(A_STG+B_STG))*2)

template <int RELU, int OUTH>
__global__ __launch_bounds__(256, 2) void gemm16(
    const __half* __restrict__ A,
    const __half* __restrict__ B,
    const float* __restrict__ bias,
    void* __restrict__ Cv,
    int N, int K)
{
    extern __shared__ __half sm16[];
    __half* As = sm16;
    __half* Bs = sm16 + NSTG * A_STG;

    const int tid = threadIdx.x;
    const int m0 = blockIdx.y * GBM;
    const int n0 = blockIdx.x * 128;
    A += (size_t)m0 * K;
    B += n0;
    bias += n0;

    const uint32_t uAs = cvta_smem(As);
    const uint32_t uBs = cvta_smem(Bs);
    const int NC = K / GBK;

    // cp.async issue for chunk c
    auto issue = [&](int c) {
        int buf = c % NSTG;
        uint32_t ab = uAs + buf * A_STG * 2;
        uint32_t bb = uBs + buf * B_STG * 2;
        #pragma unroll
        for (int t = 0; t < 2; t++) {               // A: 64x64 halves = 512 chunks
            int i = tid + t * 256;
            int r = i >> 3, kc = (i & 7) * 8;
            cp_async16(ab + 2u * (r * GAP + kc), A + (size_t)r * K + c * GBK + kc);
        }
        #pragma unroll
        for (int t = 0; t < 4; t++) {               // B: 64x128 halves = 1024 chunks
            int i = tid + t * 256;
            int r = i >> 4, nc = (i & 15) * 8;
            cp_async16(bb + 2u * (r * GBP + nc), B + (size_t)(c * GBK + r) * N + nc);
        }
        CP_COMMIT();
    };

    const int w = tid >> 5, lane = tid & 31;
    const int wm = (w & 1) * 32, wn = (w >> 1) * 32;
    const int g = lane >> 2, tg = lane & 3;
    const int lr = lane & 15;
    const int lc = (lane >> 4) * 8;

    float acc[2][4][4];
    #pragma unroll
    for (int ms = 0; ms < 2; ms++)
        #pragma unroll
        for (int ns = 0; ns < 4; ns++)
            #pragma unroll
            for (int r = 0; r < 4; r++) acc[ms][ns][r] = 0.0f;

    issue(0);
    issue(1);

    for (int c = 0; c < NC; c++) {
        if (c + 1 < NC) { CP_WAIT(1); } else { CP_WAIT(0); }
        __syncthreads();

        int buf = c % NSTG;
        uint32_t ab = uAs + buf * A_STG * 2;
        uint32_t bb = uBs + buf * B_STG * 2;
        #pragma unroll
        for (int ks = 0; ks < 4; ks++) {
            uint32_t af[2][4], bf[4][2];
            #pragma unroll
            for (int ms = 0; ms < 2; ms++) {
                uint32_t ad = ab + 2u * ((wm + ms * 16 + lr) * GAP + ks * 16 + lc);
                ldsm_x4(af[ms][0], af[ms][1], af[ms][2], af[ms][3], ad);
            }
            #pragma unroll
            for (int p = 0; p < 2; p++) {
                uint32_t ad = bb + 2u * ((ks * 16 + lr) * GBP + wn + p * 16 + lc);
                ldsm_x4_t(bf[2 * p][0], bf[2 * p][1], bf[2 * p + 1][0], bf[2 * p + 1][1], ad);
            }
            #pragma unroll
            for (int ms = 0; ms < 2; ms++)
                #pragma unroll
                for (int ns = 0; ns < 4; ns++)
                    mma16816(acc[ms][ns], af[ms], bf[ns]);
        }
        if (c + 2 < NC) issue(c + 2);
    }

    // ---- epilogue ----
    #pragma unroll
    for (int ms = 0; ms < 2; ms++) {
        #pragma unroll
        for (int ns = 0; ns < 4; ns++) {
            int row = wm + ms * 16 + g;
            int col = wn + ns * 8 + tg * 2;
            float b0 = bias[col], b1 = bias[col + 1];
            float v0 = acc[ms][ns][0] + b0;
            float v1 = acc[ms][ns][1] + b1;
            float v2 = acc[ms][ns][2] + b0;
            float v3 = acc[ms][ns][3] + b1;
            if (RELU) {
                v0 = fmaxf(v0, 0.0f); v1 = fmaxf(v1, 0.0f);
                v2 = fmaxf(v2, 0.0f); v3 = fmaxf(v3, 0.0f);
            }
            if (OUTH) {
                __half* C = (__half*)Cv + (size_t)m0 * N + n0;
                *(uint32_t*)&C[(size_t)row * N + col] = pack_half2(v0, v1);
                *(uint32_t*)&C[(size_t)(row + 8) * N + col] = pack_half2(v2, v3);
            } else {
                float* C = (float*)Cv + (size_t)m0 * N + n0;
                *(float2*)&C[(size_t)row * N + col] = make_float2(v0, v1);
                *(float2*)&C[(size_t)(row + 8) * N + col] = make_float2(v2, v3);
            }
        }
    }
}

struct QKV3 {
    const __half* W[3];
    const float* b[3];
    __half* o[3];
};

__global__ __launch_bounds__(256, 2) void gemm_qkv16(const __half* __restrict__ A, QKV3 p) {
    extern __shared__ __half sm16[];
    // replicate gemm16<0,1> body via call: simplest is to inline the same code by
    // calling a device function — but smem is declared here; forward to the kernel
    // logic by duplicating: we instead just do the same as gemm16 with z-indexed ptrs.
    __half* As = sm16;
    __half* Bs = sm16 + NSTG * A_STG;

    const int z = blockIdx.z;
    const __half* Aa = A;
    const __half* B = p.W[z];
    const float* bias = p.b[z];
    __half* C = p.o[z];
    const int N = DMODEL, K = DMODEL;

    const int tid = threadIdx.x;
    const int m0 = blockIdx.y * GBM;
    const int n0 = blockIdx.x * 128;
    Aa += (size_t)m0 * K;
    B += n0;
    bias += n0;
    C += (size_t)m0 * N + n0;

    const uint32_t uAs = cvta_smem(As);
    const uint32_t uBs = cvta_smem(Bs);
    const int NC = K / GBK;

    auto issue = [&](int c) {
        int buf = c % NSTG;
        uint32_t ab = uAs + buf * A_STG * 2;
        uint32_t bb = uBs + buf * B_STG * 2;
        #pragma unroll
        for (int t = 0; t < 2; t++) {
            int i = tid + t * 256;
            int r = i >> 3, kc = (i & 7) * 8;
            cp_async16(ab + 2u * (r * GAP + kc), Aa + (size_t)r * K + c * GBK + kc);
        }
        #pragma unroll
        for (int t = 0; t < 4; t++) {
            int i = tid + t * 256;
            int r = i >> 4, nc = (i & 15) * 8;
            cp_async16(bb + 2u * (r * GBP + nc), B + (size_t)(c * GBK + r) * N + nc);
        }
        CP_COMMIT();
    };

    const int w = tid >> 5, lane = tid & 31;
    const int wm = (w & 1) * 32, wn = (w >> 1) * 32;
    const int g = lane >> 2, tg = lane & 3;
    const int lr = lane & 15;
    const int lc = (lane >> 4) * 8;

    float acc[2][4][4];
    #pragma unroll
    for (int ms = 0; ms < 2; ms++)
        #pragma unroll
        for (int ns = 0; ns < 4; ns++)
            #pragma unroll
            for (int r = 0; r < 4; r++) acc[ms][ns][r] = 0.0f;

    issue(0);
    issue(1);

    for (int c = 0; c < NC; c++) {
        if (c + 1 < NC) { CP_WAIT(1); } else { CP_WAIT(0); }
        __syncthreads();
        int buf = c % NSTG;
        uint32_t ab = uAs + buf * A_STG * 2;
        uint32_t bb = uBs + buf * B_STG * 2;
        #pragma unroll
        for (int ks = 0; ks < 4; ks++) {
            uint32_t af[2][4], bf[4][2];
            #pragma unroll
            for (int ms = 0; ms < 2; ms++) {
                uint32_t ad = ab + 2u * ((wm + ms * 16 + lr) * GAP + ks * 16 + lc);
                ldsm_x4(af[ms][0], af[ms][1], af[ms][2], af[ms][3], ad);
            }
            #pragma unroll
            for (int p = 0; p < 2; p++) {
                uint32_t ad = bb + 2u * ((ks * 16 + lr) * GBP + wn + p * 16 + lc);
                ldsm_x4_t(bf[2 * p][0], bf[2 * p][1], bf[2 * p + 1][0], bf[2 * p + 1][1], ad);
            }
            #pragma unroll
            for (int ms = 0; ms < 2; ms++)
                #pragma unroll
                for (int ns = 0; ns < 4; ns++)
                    mma16816(acc[ms][ns], af[ms], bf[ns]);
        }
        if (c + 2 < NC) issue(c + 2);
    }

    #pragma unroll
    for (int ms = 0; ms < 2; ms++) {
        #pragma unroll
        for (int ns = 0; ns < 4; ns++) {
            int row = wm + ms * 16 + g;
            int col = wn + ns * 8 + tg * 2;
            float b0 = bias[col], b1 = bias[col + 1];
            *(uint32_t*)&C[(size_t)row * N + col] =
                pack_half2(acc[ms][ns][0] + b0, acc[ms][ns][1] + b1);
            *(uint32_t*)&C[(size_t)(row + 8) * N + col] =
                pack_half2(acc[ms][ns][2] + b0, acc[ms][ns][3] + b1);
        }
    }
}

// ================= fused attention (fp16 in, fp32 softmax, fp32 aw, fp16 ctx) ========
#define ATT_HALVES (128*72 + 128*72 + 128*72 + 128*136)
#define ATT_SMEM   (ATT_HALVES*2 + (4*128 + 128 + 128)*4)

__global__ __launch_bounds__(256) void attn_fused(const __half* __restrict__ q,
                                                  const __half* __restrict__ k,
                                                  const __half* __restrict__ v,
                                                  float* __restrict__ aw,
                                                  __half* __restrict__ ctx) {
    extern __shared__ char smc[];
    __half* Qs = (__half*)smc;              // [128][72]
    __half* Ks = Qs + 128 * 72;             // [128][72]
    __half* Vs = Ks + 128 * 72;             // [128][72]
    __half* Ps = Vs + 128 * 72;             // [128][136]
    float* red  = (float*)(Ps + 128 * 136); // [4][128]
    float* mrow = red + 4 * 128;
    float* srow = mrow + 128;

    const int tid = threadIdx.x;
    const int mt = blockIdx.x, bh = blockIdx.y;
    const int b = bh >> 4, hh = bh & 15;
    const __half* qb = q + (size_t)(b * SEQ + mt * 128) * DMODEL + hh * DK;
    const __half* kb = k + (size_t)b * SEQ * DMODEL + hh * DK;
    const __half* vb = v + (size_t)b * SEQ * DMODEL + hh * DK;
    float* awb = aw + (size_t)bh * SEQ * SEQ + (size_t)(mt * 128) * SEQ;

    const int w = tid >> 5, lane = tid & 31, g = lane >> 2, tg = lane & 3;
    const int wm = (w & 1) * 64, wn = (w >> 1) * 32, wni = w >> 1;   // S tile 2x4 warps
    const int wm2 = (w & 3) * 32, wn2 = (w >> 2) * 32;               // PV tile 4x2 warps
    const int lr = lane & 15;
    const int lc = (lane >> 4) * 8;
    const int nB = (lane & 7) + ((lane >> 4) << 3);   // non-trans B: n row
    const int kB = ((lane >> 3) & 1) * 8;             // non-trans B: k col group

    const uint32_t uQs = cvta_smem(Qs);
    const uint32_t uKs = cvta_smem(Ks);
    const uint32_t uVs = cvta_smem(Vs);
    const uint32_t uPs = cvta_smem(Ps);

    // ---- load Q tile once (fp16 direct) ----
    #pragma unroll
    for (int t = 0; t < 4; t++) {
        int i = tid + t * 256;
        int r = i >> 3, c = (i & 7) * 8;
        *(uint4*)&Qs[r * 72 + c] = *(const uint4*)(qb + (size_t)r * DMODEL + c);
    }
    if (tid < 128) { mrow[tid] = -INFINITY; srow[tid] = 0.0f; }
    __syncthreads();

    // =========================== PASS 1: row max & sum ==============================
    for (int kt = 0; kt < 8; kt++) {
        #pragma unroll
        for (int t = 0; t < 4; t++) {
            int i = tid + t * 256;
            int r = i >> 3, c = (i & 7) * 8;
            *(uint4*)&Ks[r * 72 + c] = *(const uint4*)(kb + (size_t)(kt * 128 + r) * DMODEL + c);
        }
        __syncthreads();

        float acc[4][4][4];
        #pragma unroll
        for (int ms = 0; ms < 4; ms++)
            #pragma unroll
            for (int ns = 0; ns < 4; ns++)
                #pragma unroll
                for (int r = 0; r < 4; r++) acc[ms][ns][r] = 0.0f;

        #pragma unroll
        for (int ks = 0; ks < 4; ks++) {
            uint32_t af[4][4], bf[4][2];
            #pragma unroll
            for (int ms = 0; ms < 4; ms++) {
                uint32_t ad = uQs + 2u * ((wm + ms * 16 + lr) * 72 + ks * 16 + lc);
                ldsm_x4(af[ms][0], af[ms][1], af[ms][2], af[ms][3], ad);
            }
            #pragma unroll
            for (int p = 0; p < 2; p++) {
                int n = wn + p * 16 + nB;
                uint32_t ad = uKs + 2u * (n * 72 + ks * 16 + kB);
                ldsm_x4(bf[2 * p][0], bf[2 * p][1], bf[2 * p + 1][0], bf[2 * p + 1][1], ad);
            }
            #pragma unroll
            for (int ms = 0; ms < 4; ms++)
                #pragma unroll
                for (int ns = 0; ns < 4; ns++)
                    mma16816(acc[ms][ns], af[ms], bf[ns]);
        }
        #pragma unroll
        for (int ms = 0; ms < 4; ms++)
            #pragma unroll
            for (int ns = 0; ns < 4; ns++)
                #pragma unroll
                for (int r = 0; r < 4; r++) acc[ms][ns][r] *= 0.125f;

        // row max of this tile
        #pragma unroll
        for (int ms = 0; ms < 4; ms++) {
            #pragma unroll
            for (int half = 0; half < 2; half++) {
                float rm = -INFINITY;
                #pragma unroll
                for (int ns = 0; ns < 4; ns++)
                    rm = fmaxf(rm, fmaxf(acc[ms][ns][half * 2], acc[ms][ns][half * 2 + 1]));
                rm = fmaxf(rm, __shfl_xor_sync(0xffffffffu, rm, 1));
                rm = fmaxf(rm, __shfl_xor_sync(0xffffffffu, rm, 2));
                if (tg == 0) red[wni * 128 + wm + ms * 16 + half * 8 + g] = rm;
            }
        }
        __syncthreads();
        if (tid < 128) {
            float tm = fmaxf(fmaxf(red[tid], red[128 + tid]),
                             fmaxf(red[256 + tid], red[384 + tid]));
            float mo = mrow[tid];
            float mn = fmaxf(mo, tm);
            srow[tid] *= expf(mo - mn);
            mrow[tid] = mn;
        }
        __syncthreads();
        // row sum of exp
        #pragma unroll
        for (int ms = 0; ms < 4; ms++) {
            #pragma unroll
            for (int half = 0; half < 2; half++) {
                int row = wm + ms * 16 + half * 8 + g;
                float mr = mrow[row];
                float rs = 0.0f;
                #pragma unroll
                for (int ns = 0; ns < 4; ns++)
                    rs += expf(acc[ms][ns][half * 2] - mr) + expf(acc[ms][ns][half * 2 + 1] - mr);
                rs += __shfl_xor_sync(0xffffffffu, rs, 1);
                rs += __shfl_xor_sync(0xffffffffu, rs, 2);
                if (tg == 0) red[wni * 128 + row] = rs;
            }
        }
        __syncthreads();
        if (tid < 128)
            srow[tid] += red[tid] + red[128 + tid] + red[256 + tid] + red[384 + tid];
        __syncthreads();
    }

    if (tid < 128) srow[tid] = 1.0f / srow[tid];
    __syncthreads();

    // ================== PASS 2: recompute S, write P, accumulate P@V ================
    float acc2[2][4][4];
    #pragma unroll
    for (int ms = 0; ms < 2; ms++)
        #pragma unroll
        for (int ns = 0; ns < 4; ns++)
            #pragma unroll
            for (int r = 0; r < 4; r++) acc2[ms][ns][r] = 0.0f;

    for (int kt = 0; kt < 8; kt++) {
        #pragma unroll
        for (int t = 0; t < 4; t++) {
            int i = tid + t * 256;
            int r = i >> 3, c = (i & 7) * 8;
            *(uint4*)&Ks[r * 72 + c] = *(const uint4*)(kb + (size_t)(kt * 128 + r) * DMODEL + c);
            *(uint4*)&Vs[r * 72 + c] = *(const uint4*)(vb + (size_t)(kt * 128 + r) * DMODEL + c);
        }
        __syncthreads();

        float acc[4][4][4];
        #pragma unroll
        for (int ms = 0; ms < 4; ms++)
            #pragma unroll
            for (int ns = 0; ns < 4; ns++)
                #pragma unroll
                for (int r = 0; r < 4; r++) acc[ms][ns][r] = 0.0f;

        #pragma unroll
        for (int ks = 0; ks < 4; ks++) {
            uint32_t af[4][4], bf[4][2];
            #pragma unroll
            for (int ms = 0; ms < 4; ms++) {
                uint32_t ad = uQs + 2u * ((wm + ms * 16 + lr) * 72 + ks * 16 + lc);
                ldsm_x4(af[ms][0], af[ms][1], af[ms][2], af[ms][3], ad);
            }
            #pragma unroll
            for (int p = 0; p < 2; p++) {
                int n = wn + p * 16 + nB;
                uint32_t ad = uKs + 2u * (n * 72 + ks * 16 + kB);
                ldsm_x4(bf[2 * p][0], bf[2 * p][1], bf[2 * p + 1][0], bf[2 * p + 1][1], ad);
            }
            #pragma unroll
            for (int ms = 0; ms < 4; ms++)
                #pragma unroll
                for (int ns = 0; ns < 4; ns++)
                    mma16816(acc[ms][ns], af[ms], bf[ns]);
        }

        // P = exp(S*scale - m) * (1/sum) -> smem fp16 + gmem fp32
        #pragma unroll
        for (int ms = 0; ms < 4; ms++) {
            int row0 = wm + ms * 16 + g;
            int row1 = row0 + 8;
            float m0 = mrow[row0], s0 = srow[row0];
            float m1 = mrow[row1], s1 = srow[row1];
            #pragma unroll
            for (int ns = 0; ns < 4; ns++) {
                int col = wn + ns * 8 + tg * 2;
                float p0 = expf(acc[ms][ns][0] * 0.125f - m0) * s0;
                float p1 = expf(acc[ms][ns][1] * 0.125f - m0) * s0;
                float p2 = expf(acc[ms][ns][2] * 0.125f - m1) * s1;
                float p3 = expf(acc[ms][ns][3] * 0.125f - m1) * s1;
                *(uint32_t*)&Ps[row0 * 136 + col] = pack_half2(p0, p1);
                *(uint32_t*)&Ps[row1 * 136 + col] = pack_half2(p2, p3);
                *(float2*)&awb[(size_t)row0 * SEQ + kt * 128 + col] = make_float2(p0, p1);
                *(float2*)&awb[(size_t)row1 * SEQ + kt * 128 + col] = make_float2(p2, p3);
            }
        }
        __syncthreads();

        // ctx += P @ V
        #pragma unroll
        for (int ks = 0; ks < 8; ks++) {
            uint32_t af[2][4], bf[4][2];
            #pragma unroll
            for (int ms = 0; ms < 2; ms++) {
                uint32_t ad = uPs + 2u * ((wm2 + ms * 16 + lr) * 136 + ks * 16 + lc);
                ldsm_x4(af[ms][0], af[ms][1], af[ms][2], af[ms][3], ad);
            }
            #pragma unroll
            for (int p = 0; p < 2; p++) {
                uint32_t ad = uVs + 2u * ((ks * 16 + lr) * 72 + wn2 + p * 16 + lc);
                ldsm_x4_t(bf[2 * p][0], bf[2 * p][1], bf[2 * p + 1][0], bf[2 * p + 1][1], ad);
            }
            #pragma unroll
            for (int ms = 0; ms < 2; ms++)
                #pragma unroll
                for (int ns = 0; ns < 4; ns++)
                    mma16816(acc2[ms][ns], af[ms], bf[ns]);
        }
        __syncthreads();
    }

    // ---- write ctx tile (fp16) ----
    __half* cb = ctx + (size_t)(b * SEQ + mt * 128) * DMODEL + hh * DK;
    #pragma unroll
    for (int ms = 0; ms < 2; ms++) {
        #pragma unroll
        for (int ns = 0; ns < 4; ns++) {
            int row = wm2 + ms * 16 + g;
            int col = wn2 + ns * 8 + tg * 2;
            *(uint32_t*)&cb[(size_t)row * DMODEL + col] =
                pack_half2(acc2[ms][ns][0], acc2[ms][ns][1]);
            *(uint32_t*)&cb[(size_t)(row + 8) * DMODEL + col] =
                pack_half2(acc2[ms][ns][2], acc2[ms][ns][3]);
        }
    }
}

// ------------------------- embedding + positional encoding -------------------------
__global__ void embed_kernel(const int* __restrict__ ids, const float* __restrict__ emb,
                             float* __restrict__ h, __half* __restrict__ h16) {
    int token = blockIdx.x;
    int d = blockIdx.y * 256 + threadIdx.x;
    int s = token & (SEQ - 1);
    int id = ids[token];
    float c_even = (float)((d >> 1) << 1);
    float div = __expf(c_even * (-logf(10000.0f) / (float)DMODEL));
    float ang = (float)s * div;
    float pe = (d & 1) ? cosf(ang) : sinf(ang);
    float val = emb[(size_t)id * DMODEL + d] * 32.0f + pe;
    h[(size_t)token * DMODEL + d] = val;
    h16[(size_t)token * DMODEL + d] = __float2half_rn(val);
}

// ------------------------- fused residual-add + LayerNorm (dual write) -------------
__global__ void add_ln_kernel(const float* __restrict__ x, const float* __restrict__ r,
                              const float* __restrict__ g, const float* __restrict__ b,
                              float* __restrict__ out, __half* __restrict__ out16) {
    const size_t row = blockIdx.x;
    const int tid = threadIdx.x;
    __shared__ float red[256];
    __shared__ float s_mu, s_rinv;
    float v[4];
    float s = 0.0f;
    #pragma unroll
    for (int i = 0; i < 4; i++) {
        int c = tid + i * 256;
        v[i] = x[row * DMODEL + c] + r[row * DMODEL + c];
        s += v[i];
    }
    red[tid] = s; __syncthreads();
    for (int t = 128; t > 0; t >>= 1) { if (tid < t) red[tid] += red[tid + t]; __syncthreads(); }
    if (tid == 0) s_mu = red[0] * (1.0f / DMODEL);
    __syncthreads();
    float mu = s_mu;
    float sq = 0.0f;
    #pragma unroll
    for (int i = 0; i < 4; i++) { float d = v[i] - mu; sq += d * d; }
    red[tid] = sq; __syncthreads();
    for (int t = 128; t > 0; t >>= 1) { if (tid < t) red[tid] += red[tid + t]; __syncthreads(); }
    if (tid == 0) s_rinv = rsqrtf(red[0] * (1.0f / DMODEL) + LNEPS);
    __syncthreads();
    float rinv = s_rinv;
    #pragma unroll
    for (int i = 0; i < 4; i++) {
        int c = tid + i * 256;
        float o = (v[i] - mu) * rinv * g[c] + b[c];
        out[row * DMODEL + c] = o;
        out16[row * DMODEL + c] = __float2half_rn(o);
    }
}

// ====================================================================================
extern "C" void kernel_launch(void* const* d_in, const int* in_sizes, int n_in,
                              void* d_out, int out_size) {
    const int*   ids  = (const int*)  d_in[0];
    const float* emb  = (const float*)d_in[1];
    const float* Wq   = (const float*)d_in[2];
    const float* bq   = (const float*)d_in[3];
    const float* Wk   = (const float*)d_in[4];
    const float* bk   = (const float*)d_in[5];
    const float* Wv   = (const float*)d_in[6];
    const float* bv   = (const float*)d_in[7];
    const float* Wo   = (const float*)d_in[8];
    const float* bo   = (const float*)d_in[9];
    const float* W1   = (const float*)d_in[10];
    const float* b1   = (const float*)d_in[11];
    const float* W2   = (const float*)d_in[12];
    const float* b2   = (const float*)d_in[13];
    const float* ln1g = (const float*)d_in[14];
    const float* ln1b = (const float*)d_in[15];
    const float* ln2g = (const float*)d_in[16];
    const float* ln2b = (const float*)d_in[17];

    float* out = (float*)d_out;

    float *h, *res;
    __half *h16, *q16, *k16, *v16, *ctx16, *ff16;
    __half *wq16, *wk16, *wv16, *wo16, *w116, *w216;
    cudaGetSymbolAddress((void**)&h,    g_h);
    cudaGetSymbolAddress((void**)&res,  g_res);
    cudaGetSymbolAddress((void**)&h16,  g_h16);
    cudaGetSymbolAddress((void**)&q16,  g_q16);
    cudaGetSymbolAddress((void**)&k16,  g_k16);
    cudaGetSymbolAddress((void**)&v16,  g_v16);
    cudaGetSymbolAddress((void**)&ctx16, g_ctx16);
    cudaGetSymbolAddress((void**)&ff16, g_ff16);
    cudaGetSymbolAddress((void**)&wq16, g_wq16);
    cudaGetSymbolAddress((void**)&wk16, g_wk16);
    cudaGetSymbolAddress((void**)&wv16, g_wv16);
    cudaGetSymbolAddress((void**)&wo16, g_wo16);
    cudaGetSymbolAddress((void**)&w116, g_w116);
    cudaGetSymbolAddress((void**)&w216, g_w216);

    cudaFuncSetAttribute(attn_fused, cudaFuncAttributeMaxDynamicSharedMemorySize, ATT_SMEM);
    cudaFuncSetAttribute(gemm16<0,0>, cudaFuncAttributeMaxDynamicSharedMemorySize, GSMEM);
    cudaFuncSetAttribute(gemm16<0,1>, cudaFuncAttributeMaxDynamicSharedMemorySize, GSMEM);
    cudaFuncSetAttribute(gemm16<1,1>, cudaFuncAttributeMaxDynamicSharedMemorySize, GSMEM);
    cudaFuncSetAttribute(gemm_qkv16,  cudaFuncAttributeMaxDynamicSharedMemorySize, GSMEM);

    // ---- convert weights to fp16 (once per launch) ----
    {
        int nDD = NLAYER * DMODEL * DMODEL / 4;   // float4 groups
        int nDF = NLAYER * DMODEL * FF / 4;
        f32to16<<<(nDD + 255) / 256, 256>>>(Wq, wq16, nDD);
        f32to16<<<(nDD + 255) / 256, 256>>>(Wk, wk16, nDD);
        f32to16<<<(nDD + 255) / 256, 256>>>(Wv, wv16, nDD);
        f32to16<<<(nDD + 255) / 256, 256>>>(Wo, wo16, nDD);
        f32to16<<<(nDF + 255) / 256, 256>>>(W1, w116, nDF);
        f32to16<<<(nDF + 255) / 256, 256>>>(W2, w216, nDF);
    }

    embed_kernel<<<dim3(TOK, DMODEL / 256), 256>>>(ids, emb, h, h16);

    dim3 gDD(DMODEL / 128, TOK / GBM);       // (8, 32)
    dim3 gDF(FF / 128, TOK / GBM);           // (32, 32)
    dim3 gQKV(DMODEL / 128, TOK / GBM, 3);   // (8, 32, 3)
    dim3 gFA(SEQ / 128, BATCH * NHEAD);      // (8, 32)

    for (int l = 0; l < NLAYER; l++) {
        float* aw = out + H_ELEMS + (size_t)l * AW_PER_LAYER;

        QKV3 p;
        p.W[0] = wq16 + (size_t)l * DMODEL * DMODEL;
        p.W[1] = wk16 + (size_t)l * DMODEL * DMODEL;
        p.W[2] = wv16 + (size_t)l * DMODEL * DMODEL;
        p.b[0] = bq + (size_t)l * DMODEL;
        p.b[1] = bk + (size_t)l * DMODEL;
        p.b[2] = bv + (size_t)l * DMODEL;
        p.o[0] = q16; p.o[1] = k16; p.o[2] = v16;

        gemm_qkv16<<<gQKV, 256, GSMEM>>>(h16, p);

        attn_fused<<<gFA, 256, ATT_SMEM>>>(q16, k16, v16, aw, ctx16);

        gemm16<0,0><<<gDD, 256, GSMEM>>>(ctx16, wo16 + (size_t)l * DMODEL * DMODEL,
                                         bo + (size_t)l * DMODEL, res, DMODEL, DMODEL);
        add_ln_kernel<<<TOK, 256>>>(h, res, ln1g + (size_t)l * DMODEL,
                                    ln1b + (size_t)l * DMODEL, h, h16);

        gemm16<1,1><<<gDF, 256, GSMEM>>>(h16, w116 + (size_t)l * DMODEL * FF,
                                         b1 + (size_t)l * FF, ff16, FF, DMODEL);
        gemm16<0,0><<<gDD, 256, GSMEM>>>(ff16, w216 + (size_t)l * FF * DMODEL,
                                         b2 + (size_t)l * DMODEL, res, DMODEL, FF);

        float* dst = (l == NLAYER - 1) ? out : h;
        add_ln_kernel<<<TOK, 256>>>(h, res, ln2g + (size_t)l * DMODEL,
                                    ln2b + (size_t)l * DMODEL, dst, h16);
    }
}